// round 4
// baseline (speedup 1.0000x reference)
#include <cuda_runtime.h>
#include <cuda_bf16.h>
#include <cstddef>
#include <cstdint>

// Problem constants
#define N_TOK   32768        // B*T
#define DIM     128
#define KCODES  1024
#define NCB     8
#define M_TILE  128          // tokens per block
#define KC      128          // codes per smem chunk
#define TPB     512
#define GRID_MAIN (N_TOK / M_TILE)            // 256
#define NCHUNK  (NCB * KCODES / KC)           // 64
#define RPAD    66           // float2 per row: 528B = 33 x 16B (odd) -> LDS.128 conflict-free

// Scratch (no allocations allowed -> device globals)
__device__ float g_wn[NCB * KCODES];
__device__ float g_part[GRID_MAIN];

// ---------------------------------------------------------------------------
__device__ __forceinline__ unsigned long long ffma2(unsigned long long a,
                                                    unsigned long long b,
                                                    unsigned long long c) {
    unsigned long long d;
    asm("fma.rn.f32x2 %0, %1, %2, %3;" : "=l"(d) : "l"(a), "l"(b), "l"(c));
    return d;
}
__device__ __forceinline__ unsigned long long pack2(float lo, float hi) {
    unsigned long long v;
    asm("mov.b64 %0, {%1, %2};" : "=l"(v) : "f"(lo), "f"(hi));
    return v;
}
__device__ __forceinline__ void unpack2(unsigned long long v, float& lo, float& hi) {
    asm("mov.b64 {%0, %1}, %2;" : "=f"(lo), "=f"(hi) : "l"(v));
}
__device__ __forceinline__ void cp_async16(uint32_t dst_smem, const void* src) {
    asm volatile("cp.async.cg.shared.global [%0], [%1], 16;\n"
                 :: "r"(dst_smem), "l"(src));
}
#define CP_COMMIT() asm volatile("cp.async.commit_group;\n" ::: "memory")
#define CP_WAIT(n)  asm volatile("cp.async.wait_group %0;\n" :: "n"(n) : "memory")

// ---------------------------------------------------------------------------
// Shared memory (~214 KB)
// ---------------------------------------------------------------------------
struct SB {
    float2 res[M_TILE][RPAD];          // 67.6 KB residual (row 528B)
    float2 code[2][KC][RPAD];          // 135 KB double-buffered code chunk
    float  wn[KCODES];                 // ||w||^2 current codebook
    int    idx[M_TILE];
    int    codes_all[NCB][M_TILE];
    float  red[TPB];
};

extern __shared__ char smraw[];

// ---------------------------------------------------------------------------
// Kernel 1: ||w||^2 per code (warp per code; lane-strided + xor tree)
// ---------------------------------------------------------------------------
__global__ void wnorm_kernel(const float* __restrict__ cb) {
    int gwarp = (blockIdx.x * blockDim.x + threadIdx.x) >> 5;
    int lane  = threadIdx.x & 31;
    if (gwarp >= NCB * KCODES) return;
    const float* w = cb + (size_t)gwarp * DIM;
    float s = 0.f;
    #pragma unroll
    for (int i = 0; i < DIM / 32; ++i) {
        float v = w[lane + 32 * i];
        s = __fmaf_rn(v, v, s);
    }
    #pragma unroll
    for (int o = 16; o > 0; o >>= 1)
        s = __fadd_rn(s, __shfl_xor_sync(0xFFFFFFFFu, s, o));
    if (lane == 0) g_wn[gwarp] = s;
}

// ---------------------------------------------------------------------------
// stage one code chunk (128 rows x 512B payload into 528B-padded rows), 16B cp.async
// ---------------------------------------------------------------------------
__device__ __forceinline__ void stage_chunk(SB* sm, const float4* cb4,
                                            int t, int tid) {
    const float4* src = cb4 + (size_t)t * (KC * DIM / 4);
    int buf = t & 1;
    #pragma unroll
    for (int r = 0; r < (KC * DIM / 4) / TPB; ++r) {   // 8 per thread
        int e  = tid + r * TPB;
        int kl = e >> 5, q = e & 31;                   // 32 float4 per row
        uint32_t dst = (uint32_t)__cvta_generic_to_shared(
            reinterpret_cast<char*>(&sm->code[buf][kl][0]) + q * 16);
        cp_async16(dst, src + e);
    }
    CP_COMMIT();
}

// ---------------------------------------------------------------------------
// Kernel 2: main residual-VQ. Block owns 128 tokens; warp owns 8 tokens and
// scans all codes (lane = code lane+32j). Scoring chain byte-identical to
// the validated kernel: acc = ffma2 over d2 ascending (lo,hi per pair);
//   u = fadd( fma(-2, fadd(lo,hi), rr), wn ) ; argmin first-index ties.
// ---------------------------------------------------------------------------
__global__ __launch_bounds__(TPB, 1) void rvq_main(
    const float* __restrict__ emb, const float* __restrict__ cb,
    float* __restrict__ out_codes, float* __restrict__ out_quant)
{
    SB* sm = reinterpret_cast<SB*>(smraw);
    const int tid  = threadIdx.x;
    const int wid  = tid >> 5;          // 16 warps; warp owns tokens wid*8..+7
    const int lane = tid & 31;
    const int n0   = blockIdx.x * M_TILE;
    const float4* cb4 = reinterpret_cast<const float4*>(cb);

    // residual <- embeddings
    for (int e = tid; e < M_TILE * DIM; e += TPB) {
        int m = e >> 7, d = e & (DIM - 1);
        reinterpret_cast<float*>(&sm->res[m][0])[d] = emb[(size_t)(n0 + m) * DIM + d];
    }

    stage_chunk(sm, cb4, 0, tid);

    float lsum = 0.f;

    for (int c = 0; c < NCB; ++c) {
        const float* cbc = cb + (size_t)c * KCODES * DIM;

        __syncthreads();   // residual writes visible

        // rr[i] for this warp's 8 tokens (lane-strided + xor tree; all lanes
        // end with the full sum). Chain identical to validated kernel.
        float rrv[8];
        #pragma unroll
        for (int i = 0; i < 8; ++i) {
            const float* row = reinterpret_cast<const float*>(&sm->res[wid * 8 + i][0]);
            float s = 0.f;
            #pragma unroll
            for (int q = 0; q < DIM / 32; ++q) {
                float v = row[lane + 32 * q];
                s = __fmaf_rn(v, v, s);
            }
            #pragma unroll
            for (int o = 16; o > 0; o >>= 1)
                s = __fadd_rn(s, __shfl_xor_sync(0xFFFFFFFFu, s, o));
            rrv[i] = s;
        }
        // stage ||w||^2 for this codebook
        for (int e = tid; e < KCODES; e += TPB)
            sm->wn[e] = g_wn[c * KCODES + e];

        float bU[8]; int bI[8];
        #pragma unroll
        for (int i = 0; i < 8; ++i) { bU[i] = 1e30f; bI[i] = 0; }

        for (int tch = c * 8; tch < c * 8 + 8; ++tch) {
            const int kb  = (tch & 7) * KC;
            const int buf = tch & 1;

            if (tch + 1 < NCHUNK) { stage_chunk(sm, cb4, tch + 1, tid); CP_WAIT(1); }
            else                  { CP_WAIT(0); }
            __syncthreads();      // chunk tch ready (+ rr/wn on first chunk)

            unsigned long long acc[8][4];
            #pragma unroll
            for (int i = 0; i < 8; ++i)
                #pragma unroll
                for (int j = 0; j < 4; ++j) acc[i][j] = 0ull;

            // d2-pairs: float4 = dims (2p, 2p+1); apply lo then hi -> same
            // single-accumulator d2-ascending chain as before.
            #pragma unroll 2
            for (int p = 0; p < DIM / 4; ++p) {
                float4 b[4];
                #pragma unroll
                for (int j = 0; j < 4; ++j)
                    b[j] = *reinterpret_cast<const float4*>(
                        reinterpret_cast<const char*>(&sm->code[buf][lane + 32 * j][0]) + p * 16);
                unsigned long long blo[4], bhi[4];
                #pragma unroll
                for (int j = 0; j < 4; ++j) {
                    blo[j] = pack2(b[j].x, b[j].y);
                    bhi[j] = pack2(b[j].z, b[j].w);
                }
                #pragma unroll
                for (int i = 0; i < 8; ++i) {
                    float4 a = *reinterpret_cast<const float4*>(
                        reinterpret_cast<const char*>(&sm->res[wid * 8 + i][0]) + p * 16);
                    unsigned long long alo = pack2(a.x, a.y);
                    unsigned long long ahi = pack2(a.z, a.w);
                    #pragma unroll
                    for (int j = 0; j < 4; ++j) {
                        acc[i][j] = ffma2(alo, blo[j], acc[i][j]);
                        acc[i][j] = ffma2(ahi, bhi[j], acc[i][j]);
                    }
                }
            }

            // score + running argmin (k ascends over (tch, j) per lane)
            #pragma unroll
            for (int j = 0; j < 4; ++j) {
                int   kl = lane + 32 * j;
                float wn = sm->wn[kb + kl];
                int   k  = kb + kl;
                #pragma unroll
                for (int i = 0; i < 8; ++i) {
                    float lo, hi; unpack2(acc[i][j], lo, hi);
                    float m_ = __fadd_rn(lo, hi);
                    float t_ = __fmaf_rn(-2.0f, m_, rrv[i]);
                    float u  = __fadd_rn(t_, wn);
                    if (u < bU[i]) { bU[i] = u; bI[i] = k; }
                }
            }
            __syncthreads();      // compute done before buf refilled
        }

        // warp-local argmin over 32 lanes ((minU, minK-on-tie) associative ->
        // identical to first-index linear scan)
        #pragma unroll
        for (int i = 0; i < 8; ++i) {
            float u = bU[i]; int k = bI[i];
            #pragma unroll
            for (int o = 1; o < 32; o <<= 1) {
                float ou = __shfl_xor_sync(0xFFFFFFFFu, u, o);
                int   ok = __shfl_xor_sync(0xFFFFFFFFu, k, o);
                if (ou < u || (ou == u && ok < k)) { u = ou; k = ok; }
            }
            if (lane == 0) {
                int m = wid * 8 + i;
                sm->idx[m] = k;
                sm->codes_all[c][m] = k;
                out_codes[(size_t)(n0 + m) * NCB + c] = (float)k;
            }
        }
        __syncthreads();   // idx visible to update loop

        // residual update (exact reference chain) + loss accumulation
        for (int e = tid; e < M_TILE * DIM; e += TPB) {
            int m = e >> 7, d = e & (DIM - 1);
            float w = cbc[(size_t)sm->idx[m] * DIM + d];
            float* rp = &reinterpret_cast<float*>(&sm->res[m][0])[d];
            float r = __fadd_rn(*rp, -w);
            *rp = r;
            lsum += r * r;
        }
    }

    // quantized output: q = sum_c w[idx_c] (reference add chain from 0),
    // then straight-through: out = e + (q - e)
    __syncthreads();
    for (int e = tid; e < M_TILE * DIM; e += TPB) {
        int m = e >> 7, d = e & (DIM - 1);
        float q = cb[(size_t)sm->codes_all[0][m] * DIM + d];
        #pragma unroll
        for (int c = 1; c < NCB; ++c)
            q = __fadd_rn(q, cb[(size_t)c * KCODES * DIM
                               + (size_t)sm->codes_all[c][m] * DIM + d]);
        size_t g = (size_t)(n0 + m) * DIM + d;
        float e0 = emb[g];
        out_quant[g] = __fadd_rn(e0, __fadd_rn(q, -e0));
    }

    // deterministic block loss reduction
    sm->red[tid] = lsum;
    __syncthreads();
    for (int s = TPB / 2; s > 0; s >>= 1) {
        if (tid < s) sm->red[tid] += sm->red[tid + s];
        __syncthreads();
    }
    if (tid == 0) g_part[blockIdx.x] = sm->red[0];
}

// ---------------------------------------------------------------------------
__global__ void loss_final(float* __restrict__ out_loss) {
    __shared__ float red[GRID_MAIN];
    int t = threadIdx.x;
    red[t] = g_part[t];
    __syncthreads();
    for (int s = GRID_MAIN / 2; s > 0; s >>= 1) {
        if (t < s) red[t] += red[t + s];
        __syncthreads();
    }
    if (t == 0)
        out_loss[0] = red[0] * (1.0f / ((float)N_TOK * (float)DIM * (float)NCB));
}

// ---------------------------------------------------------------------------
extern "C" void kernel_launch(void* const* d_in, const int* in_sizes, int n_in,
                              void* d_out, int out_size) {
    const float* emb = (const float*)d_in[0];   // [8,4096,128] f32
    const float* cb  = (const float*)d_in[1];   // [8,1024,128] f32

    float* out_codes = (float*)d_out;                         // 32768*8
    float* out_quant = out_codes + (size_t)N_TOK * NCB;       // 32768*128
    float* out_loss  = out_quant + (size_t)N_TOK * DIM;       // 1

    cudaFuncSetAttribute(rvq_main, cudaFuncAttributeMaxDynamicSharedMemorySize,
                         (int)sizeof(SB));

    wnorm_kernel<<<(NCB * KCODES) / 8, 256>>>(cb);
    rvq_main<<<GRID_MAIN, TPB, sizeof(SB)>>>(emb, cb, out_codes, out_quant);
    loss_final<<<1, GRID_MAIN>>>(out_loss);
}

// round 5
// speedup vs baseline: 1.0910x; 1.0910x over previous
#include <cuda_runtime.h>
#include <cuda_bf16.h>
#include <cstddef>
#include <cstdint>

// Problem constants
#define N_TOK   32768        // B*T
#define DIM     128
#define KCODES  1024
#define NCB     8
#define M_TILE  128          // tokens per block
#define KC      128          // codes per smem chunk
#define TPB     256
#define GRID_MAIN (N_TOK / M_TILE)            // 256
#define NCHUNK  (NCB * KCODES / KC)           // 64
#define RPAD    65           // res row: 65 float2 = 520B
#define CSTR    129          // code_t row stride in float2 (odd -> optimal STS scatter)

// Scratch (no allocations allowed -> device globals)
__device__ float g_wn[NCB * KCODES];
__device__ float g_part[GRID_MAIN];

// ---------------------------------------------------------------------------
__device__ __forceinline__ unsigned long long ffma2(unsigned long long a,
                                                    unsigned long long b,
                                                    unsigned long long c) {
    unsigned long long d;
    asm("fma.rn.f32x2 %0, %1, %2, %3;" : "=l"(d) : "l"(a), "l"(b), "l"(c));
    return d;
}
__device__ __forceinline__ void unpack2(unsigned long long v, float& lo, float& hi) {
    asm("mov.b64 {%0, %1}, %2;" : "=f"(lo), "=f"(hi) : "l"(v));
}
__device__ __forceinline__ void cp_async8(uint32_t dst_smem, const void* src) {
    asm volatile("cp.async.ca.shared.global [%0], [%1], 8;\n"
                 :: "r"(dst_smem), "l"(src));
}
#define CP_COMMIT() asm volatile("cp.async.commit_group;\n" ::: "memory")
#define CP_WAIT(n)  asm volatile("cp.async.wait_group %0;\n" :: "n"(n) : "memory")

// ---------------------------------------------------------------------------
// Shared memory (~203 KB)
//   res   [m][d2]  : warp-private token rows (a-loads are full-warp broadcast)
//   code_t[d2][k]  : TRANSPOSED chunk; b-loads are lane-linear (optimal 2 wf)
// ---------------------------------------------------------------------------
struct SB {
    float2 res[M_TILE][RPAD];          // 66.5 KB
    float2 code[2][DIM / 2][CSTR];     // 129 KB  double-buffered, transposed
    float  wn[KCODES];                 // 4 KB
    int    codes_all[NCB][M_TILE];     // 4 KB
    float  red[TPB];
};

extern __shared__ char smraw[];

// ---------------------------------------------------------------------------
// Kernel 1: ||w||^2 per code (warp per code; lane-strided + xor tree)
// ---------------------------------------------------------------------------
__global__ void wnorm_kernel(const float* __restrict__ cb) {
    int gwarp = (blockIdx.x * blockDim.x + threadIdx.x) >> 5;
    int lane  = threadIdx.x & 31;
    if (gwarp >= NCB * KCODES) return;
    const float* w = cb + (size_t)gwarp * DIM;
    float s = 0.f;
    #pragma unroll
    for (int i = 0; i < DIM / 32; ++i) {
        float v = w[lane + 32 * i];
        s = __fmaf_rn(v, v, s);
    }
    #pragma unroll
    for (int o = 16; o > 0; o >>= 1)
        s = __fadd_rn(s, __shfl_xor_sync(0xFFFFFFFFu, s, o));
    if (lane == 0) g_wn[gwarp] = s;
}

// ---------------------------------------------------------------------------
// stage one code chunk TRANSPOSED: gmem float2 e = k*64 + d2  ->  code_t[d2][k]
// dst scatter stride 129*8B (odd 8B units) -> each bank hit exactly twice.
// ---------------------------------------------------------------------------
__device__ __forceinline__ void stage_chunk(SB* sm, const float2* cb2,
                                            int t, int tid) {
    const float2* src = cb2 + (size_t)t * (KC * DIM / 2);
    int buf = t & 1;
    #pragma unroll
    for (int r = 0; r < (KC * DIM / 2) / TPB; ++r) {   // 32 per thread
        int e  = tid + r * TPB;
        int k  = e >> 6, d2 = e & 63;
        uint32_t dst = (uint32_t)__cvta_generic_to_shared(&sm->code[buf][d2][k]);
        cp_async8(dst, src + e);
    }
    CP_COMMIT();
}

// ---------------------------------------------------------------------------
// Kernel 2: main residual-VQ. Warp owns 16 tokens end-to-end (no cross-warp
// residual sharing); lane owns 4 codes of each 128-code chunk.
// Scoring chain byte-identical to the validated kernel:
//   acc = ffma2 over d2 ascending;  u = fadd( fma(-2, fadd(lo,hi), rr), wn )
//   argmin, first-index ties (k ascends over (chunk, j) per lane; warp
//   xor-tree with (u, k-min-on-tie) rule).
// ---------------------------------------------------------------------------
__global__ __launch_bounds__(TPB, 1) void rvq_main(
    const float* __restrict__ emb, const float* __restrict__ cb,
    float* __restrict__ out_codes, float* __restrict__ out_quant)
{
    SB* sm = reinterpret_cast<SB*>(smraw);
    const int tid  = threadIdx.x;
    const int wid  = tid >> 5;          // 8 warps; warp owns tokens wid*16..+15
    const int lane = tid & 31;
    const int n0   = blockIdx.x * M_TILE;
    const float2* cb2 = reinterpret_cast<const float2*>(cb);

    stage_chunk(sm, cb2, 0, tid);

    // residual <- embeddings (warp-private rows) + rr (validated chain:
    // fmaf over q ascending, then xor tree; all lanes end with full sum)
    float rrv[16];
    #pragma unroll
    for (int i = 0; i < 16; ++i) {
        int m = wid * 16 + i;
        const float* er = emb + (size_t)(n0 + m) * DIM;
        float* rowf = reinterpret_cast<float*>(&sm->res[m][0]);
        float s = 0.f;
        #pragma unroll
        for (int q = 0; q < DIM / 32; ++q) {
            int d = lane + 32 * q;
            float v = er[d];
            rowf[d] = v;
            s = __fmaf_rn(v, v, s);
        }
        #pragma unroll
        for (int o = 16; o > 0; o >>= 1)
            s = __fadd_rn(s, __shfl_xor_sync(0xFFFFFFFFu, s, o));
        rrv[i] = s;
    }

    float lsum = 0.f;

    for (int c = 0; c < NCB; ++c) {
        const float* cbc = cb + (size_t)c * KCODES * DIM;

        // stage ||w||^2 for this codebook (read after next barrier)
        for (int e = tid; e < KCODES; e += TPB)
            sm->wn[e] = g_wn[c * KCODES + e];

        float bU[16]; int bI[16];
        #pragma unroll
        for (int i = 0; i < 16; ++i) { bU[i] = 1e30f; bI[i] = 0; }

        for (int tch = c * 8; tch < c * 8 + 8; ++tch) {
            const int kb  = (tch & 7) * KC;
            const int buf = tch & 1;

            if (tch + 1 < NCHUNK) { stage_chunk(sm, cb2, tch + 1, tid); CP_WAIT(1); }
            else                  { CP_WAIT(0); }
            __syncthreads();      // chunk tch ready (+ wn on first chunk of cb)

            unsigned long long acc[16][4];
            #pragma unroll
            for (int i = 0; i < 16; ++i)
                #pragma unroll
                for (int j = 0; j < 4; ++j) acc[i][j] = 0ull;

            for (int d2 = 0; d2 < DIM / 2; ++d2) {
                unsigned long long b[4];
                #pragma unroll
                for (int j = 0; j < 4; ++j)
                    b[j] = *reinterpret_cast<const unsigned long long*>(
                               &sm->code[buf][d2][lane + 32 * j]);
                #pragma unroll
                for (int i = 0; i < 16; ++i) {
                    unsigned long long a =
                        *reinterpret_cast<const unsigned long long*>(
                            &sm->res[wid * 16 + i][d2]);   // warp broadcast
                    #pragma unroll
                    for (int j = 0; j < 4; ++j)
                        acc[i][j] = ffma2(a, b[j], acc[i][j]);
                }
            }

            // u = fl(fl(rr - 2m) + ww); running argmin, k ascending per lane
            #pragma unroll
            for (int j = 0; j < 4; ++j) {
                int   kl = lane + 32 * j;
                float wn = sm->wn[kb + kl];
                int   k  = kb + kl;
                #pragma unroll
                for (int i = 0; i < 16; ++i) {
                    float lo, hi; unpack2(acc[i][j], lo, hi);
                    float m_ = __fadd_rn(lo, hi);
                    float t_ = __fmaf_rn(-2.0f, m_, rrv[i]);
                    float u  = __fadd_rn(t_, wn);
                    if (u < bU[i]) { bU[i] = u; bI[i] = k; }
                }
            }
            __syncthreads();      // all warps done with buf before refill
        }

        // warp argmin over 32 lanes; result lands in ALL lanes (xor tree),
        // so the update below needs no smem handoff for idx.
        #pragma unroll
        for (int i = 0; i < 16; ++i) {
            float u = bU[i]; int k = bI[i];
            #pragma unroll
            for (int o = 1; o < 32; o <<= 1) {
                float ou = __shfl_xor_sync(0xFFFFFFFFu, u, o);
                int   ok = __shfl_xor_sync(0xFFFFFFFFu, k, o);
                if (ou < u || (ou == u && ok < k)) { u = ou; k = ok; }
            }
            bI[i] = k;
            if (lane == 0) {
                int m = wid * 16 + i;
                sm->codes_all[c][m] = k;
                out_codes[(size_t)(n0 + m) * NCB + c] = (float)k;
            }
        }

        // fused residual update + rr for next step (exact reference chains)
        #pragma unroll
        for (int i = 0; i < 16; ++i) {
            int m = wid * 16 + i;
            const float* wrow = cbc + (size_t)bI[i] * DIM;
            float* rowf = reinterpret_cast<float*>(&sm->res[m][0]);
            float s = 0.f;
            #pragma unroll
            for (int q = 0; q < DIM / 32; ++q) {
                int d = lane + 32 * q;
                float w = wrow[d];
                float r = __fadd_rn(rowf[d], -w);
                rowf[d] = r;
                s = __fmaf_rn(r, r, s);      // rr chain (q ascending)
                lsum += r * r;               // loss (order-insensitive tol)
            }
            #pragma unroll
            for (int o = 16; o > 0; o >>= 1)
                s = __fadd_rn(s, __shfl_xor_sync(0xFFFFFFFFu, s, o));
            rrv[i] = s;
        }
    }

    // quantized output: q = sum_c w[idx_c] (reference add chain from 0),
    // straight-through: out = e + (q - e)
    __syncthreads();   // codes_all from all warps
    for (int e = tid; e < M_TILE * DIM; e += TPB) {
        int m = e >> 7, d = e & (DIM - 1);
        float q = cb[(size_t)sm->codes_all[0][m] * DIM + d];
        #pragma unroll
        for (int c = 1; c < NCB; ++c)
            q = __fadd_rn(q, cb[(size_t)c * KCODES * DIM
                               + (size_t)sm->codes_all[c][m] * DIM + d]);
        size_t g = (size_t)(n0 + m) * DIM + d;
        float e0 = emb[g];
        out_quant[g] = __fadd_rn(e0, __fadd_rn(q, -e0));
    }

    // deterministic block loss reduction
    sm->red[tid] = lsum;
    __syncthreads();
    for (int s = TPB / 2; s > 0; s >>= 1) {
        if (tid < s) sm->red[tid] += sm->red[tid + s];
        __syncthreads();
    }
    if (tid == 0) g_part[blockIdx.x] = sm->red[0];
}

// ---------------------------------------------------------------------------
__global__ void loss_final(float* __restrict__ out_loss) {
    __shared__ float red[GRID_MAIN];
    int t = threadIdx.x;
    red[t] = g_part[t];
    __syncthreads();
    for (int s = GRID_MAIN / 2; s > 0; s >>= 1) {
        if (t < s) red[t] += red[t + s];
        __syncthreads();
    }
    if (t == 0)
        out_loss[0] = red[0] * (1.0f / ((float)N_TOK * (float)DIM * (float)NCB));
}

// ---------------------------------------------------------------------------
extern "C" void kernel_launch(void* const* d_in, const int* in_sizes, int n_in,
                              void* d_out, int out_size) {
    const float* emb = (const float*)d_in[0];   // [8,4096,128] f32
    const float* cb  = (const float*)d_in[1];   // [8,1024,128] f32

    float* out_codes = (float*)d_out;                         // 32768*8
    float* out_quant = out_codes + (size_t)N_TOK * NCB;       // 32768*128
    float* out_loss  = out_quant + (size_t)N_TOK * DIM;       // 1

    cudaFuncSetAttribute(rvq_main, cudaFuncAttributeMaxDynamicSharedMemorySize,
                         (int)sizeof(SB));

    wnorm_kernel<<<(NCB * KCODES) / 8, 256>>>(cb);
    rvq_main<<<GRID_MAIN, TPB, sizeof(SB)>>>(emb, cb, out_codes, out_quant);
    loss_final<<<1, GRID_MAIN>>>(out_loss);
}